// round 6
// baseline (speedup 1.0000x reference)
#include <cuda_runtime.h>

// Problem: x (2,128,512,512) f32.
//   edge = sum_o |conv(sum_c x, sobel_o)|  (channel-independent)
//   out  = maxpool2x2(edge) broadcast to (2,128,256,256)
//
// 2-stage batch pipeline:
//   cs(b): channel sum of batch b (reads 128MB)        [main stream]
//   ec(b): edge+pool+broadcast of batch b (writes 32MB) [side stream]
// ec(b0) overlaps cs(b1); only ec(b1) exposed.

#define S_SPATIAL   (512 * 512)
#define S_SPATIAL4  (S_SPATIAL / 4)   // 65536
#define NCH         128
#define NB          2

__device__ float g_sum[NB * S_SPATIAL];     // 2 MB scratch

// ---------------- cs: channel sum for one batch (float4) ----------------
__global__ void __launch_bounds__(256) k_chansum(const float4* __restrict__ x, int b) {
    int sp = blockIdx.x * blockDim.x + threadIdx.x;   // 0 .. 65535
    if (sp >= S_SPATIAL4) return;
    const float4* p = x + (size_t)b * NCH * S_SPATIAL4 + sp;
    float4 acc = make_float4(0.f, 0.f, 0.f, 0.f);
#pragma unroll 16
    for (int c = 0; c < NCH; c++) {
        float4 v = p[(size_t)c * S_SPATIAL4];
        acc.x += v.x; acc.y += v.y; acc.z += v.z; acc.w += v.w;
    }
    ((float4*)g_sum)[(b << 16) + sp] = acc;
}

// ---------------- ec: edge+pool one pooled row, broadcast 128 channels ----------------
__device__ __forceinline__ float edge_at(const float* r0, const float* r1,
                                         const float* r2, int x0) {
    float a = r0[x0],  bb = r0[x0+1], c = r0[x0+2];
    float d = r1[x0],                  f = r1[x0+2];
    float g = r2[x0],  h = r2[x0+1],  i = r2[x0+2];
    // XLA conv = cross-correlation (no kernel flip)
    float e0 = -a + c - 2.f*d + 2.f*f - g + i;
    float e1 =  a + 2.f*bb + c - g - 2.f*h - i;
    float e2 =  2.f*a + bb + d - f - h - 2.f*i;
    float e3 = -bb - 2.f*c + d - f + 2.f*g + h;
    return fabsf(e0) + fabsf(e1) + fabsf(e2) + fabsf(e3);
}

#define SROW_W 520

__global__ void __launch_bounds__(256) k_edgecast(float4* __restrict__ out, int b) {
    int py  = blockIdx.x;            // pooled row 0..255
    int tid = threadIdx.x;           // = px, 0..255

    __shared__ float srow[4][SROW_W];   // input rows 2py-1..2py+2, x shifted +1
    __shared__ float row[256];          // pooled edge row

    const float* s = g_sum + b * S_SPATIAL;
#pragma unroll
    for (int k = tid; k < 512; k += 256) {
        int r  = k >> 7;             // 0..3
        int f4 = k & 127;
        int y  = 2 * py - 1 + r;
        float4 v = make_float4(0.f, 0.f, 0.f, 0.f);
        if (y >= 0 && y < 512)
            v = __ldg((const float4*)(s + y * 512) + f4);
        float* dst = &srow[r][1 + 4 * f4];
        dst[0] = v.x; dst[1] = v.y; dst[2] = v.z; dst[3] = v.w;
    }
    if (tid < 8) {                   // halo cols x=-1, x=512 are zero
        int r = tid >> 1;
        srow[r][(tid & 1) ? 513 : 0] = 0.f;
    }
    __syncthreads();

    {
        int xb = 2 * tid;
        const float *r0 = srow[0], *r1 = srow[1], *r2 = srow[2], *r3 = srow[3];
        row[tid] = fmaxf(
            fmaxf(edge_at(r0, r1, r2, xb), edge_at(r0, r1, r2, xb + 1)),
            fmaxf(edge_at(r1, r2, r3, xb), edge_at(r1, r2, r3, xb + 1)));
    }
    __syncthreads();

    // Broadcast write: 128 channels x 64 float4 = 8192 float4 / block.
    int px4  = tid & 63;
    int csub = tid >> 6;             // 0..3
    float4 v = ((const float4*)row)[px4];
    float4* o = out + ((size_t)(b * NCH + csub) * 256 + py) * 64 + px4;
#pragma unroll
    for (int i = 0; i < 32; i++) {
        __stcs(o, v);                // evict-first: eager writeback
        o += (size_t)4 * 256 * 64;   // advance 4 channels
    }
}

extern "C" void kernel_launch(void* const* d_in, const int* in_sizes, int n_in,
                              void* d_out, int out_size) {
    const float4* x = (const float4*)d_in[0];
    float4* out = (float4*)d_out;

    // One-time side stream + events (reused across calls; deterministic work).
    static cudaStream_t s2 = nullptr;
    static cudaEvent_t ev0, ev1, evj;
    if (!s2) {
        cudaStreamCreateWithFlags(&s2, cudaStreamNonBlocking);
        cudaEventCreateWithFlags(&ev0, cudaEventDisableTiming);
        cudaEventCreateWithFlags(&ev1, cudaEventDisableTiming);
        cudaEventCreateWithFlags(&evj, cudaEventDisableTiming);
    }

    // cs(b0) -> [ec(b0) || cs(b1)] -> ec(b1)
    k_chansum<<<256, 256>>>(x, 0);
    cudaEventRecord(ev0, 0);
    cudaStreamWaitEvent(s2, ev0, 0);
    k_edgecast<<<256, 256, 0, s2>>>(out, 0);

    k_chansum<<<256, 256>>>(x, 1);
    cudaEventRecord(ev1, 0);
    cudaStreamWaitEvent(s2, ev1, 0);
    k_edgecast<<<256, 256, 0, s2>>>(out, 1);

    cudaEventRecord(evj, s2);
    cudaStreamWaitEvent(0, evj, 0);
}

// round 7
// speedup vs baseline: 1.1674x; 1.1674x over previous
#include <cuda_runtime.h>

// Problem: x (2,128,512,512) f32.
//   edge = sum_o |conv(sum_c x, sobel_o)|  (channel-independent)
//   out  = maxpool2x2(edge) broadcast to (2,128,256,256)
//
// K1: channel sum (reads 256MB, DRAM-bound) -> g_sum (2,512,512)
// K2: per (b, pooled row): stage 4 g_sum rows in smem, sobel x4 + abs-sum
//     + maxpool, broadcast-write 128 channels with WRITE-THROUGH stores so
//     the 64MB drains to DRAM during K2's idle-DRAM window instead of
//     writing back during the next replay's K1.

#define S_SPATIAL   (512 * 512)
#define S_SPATIAL4  (S_SPATIAL / 4)   // 65536
#define NCH         128
#define NB          2

__device__ float g_sum[NB * S_SPATIAL];     // 2 MB scratch

// ---------------- K1: channel sum (float4) ----------------
__global__ void __launch_bounds__(256) k_chansum(const float4* __restrict__ x) {
    int idx = blockIdx.x * blockDim.x + threadIdx.x;   // 0 .. 131071
    if (idx >= NB * S_SPATIAL4) return;
    int b  = idx >> 16;
    int sp = idx & 0xFFFF;
    const float4* p = x + (size_t)b * NCH * S_SPATIAL4 + sp;
    float4 acc = make_float4(0.f, 0.f, 0.f, 0.f);
#pragma unroll 8
    for (int c = 0; c < NCH; c++) {
        float4 v = p[(size_t)c * S_SPATIAL4];
        acc.x += v.x; acc.y += v.y; acc.z += v.z; acc.w += v.w;
    }
    ((float4*)g_sum)[idx] = acc;
}

// ---------------- K2 fused: smem-staged edge+pool row -> broadcast ----------------
__device__ __forceinline__ float edge_at(const float* r0, const float* r1,
                                         const float* r2, int x0) {
    float a = r0[x0],  bb = r0[x0+1], c = r0[x0+2];
    float d = r1[x0],                  f = r1[x0+2];
    float g = r2[x0],  h = r2[x0+1],  i = r2[x0+2];
    // XLA conv = cross-correlation (no kernel flip)
    float e0 = -a + c - 2.f*d + 2.f*f - g + i;
    float e1 =  a + 2.f*bb + c - g - 2.f*h - i;
    float e2 =  2.f*a + bb + d - f - h - 2.f*i;
    float e3 = -bb - 2.f*c + d - f + 2.f*g + h;
    return fabsf(e0) + fabsf(e1) + fabsf(e2) + fabsf(e3);
}

#define SROW_W 520   // 514 used (x = -1 .. 512), padded

__global__ void __launch_bounds__(256) k_edgecast(float4* __restrict__ out) {
    // grid = NB * 256. block = (b, pooled row py)
    int py = blockIdx.x & 255;
    int b  = blockIdx.x >> 8;
    int tid = threadIdx.x;           // = px, 0..255

    __shared__ float srow[4][SROW_W];   // input rows 2py-1..2py+2, x shifted +1
    __shared__ float row[256];          // pooled edge row

    // Stage 4 rows of g_sum, coalesced float4 (512 float4 total, 2/thread)
    const float* s = g_sum + b * S_SPATIAL;
#pragma unroll
    for (int k = tid; k < 512; k += 256) {
        int r  = k >> 7;             // 0..3
        int f4 = k & 127;
        int y  = 2 * py - 1 + r;
        float4 v = make_float4(0.f, 0.f, 0.f, 0.f);
        if (y >= 0 && y < 512)
            v = __ldg((const float4*)(s + y * 512) + f4);
        float* dst = &srow[r][1 + 4 * f4];
        dst[0] = v.x; dst[1] = v.y; dst[2] = v.z; dst[3] = v.w;
    }
    if (tid < 8) {                   // halo cols x=-1, x=512 are always zero
        int r = tid >> 1;
        srow[r][(tid & 1) ? 513 : 0] = 0.f;
    }
    __syncthreads();

    // Each thread: one pooled pixel. patch x base = 2*px-1 -> smem idx 2*px
    {
        int xb = 2 * tid;
        const float *r0 = srow[0], *r1 = srow[1], *r2 = srow[2], *r3 = srow[3];
        row[tid] = fmaxf(
            fmaxf(edge_at(r0, r1, r2, xb), edge_at(r0, r1, r2, xb + 1)),
            fmaxf(edge_at(r1, r2, r3, xb), edge_at(r1, r2, r3, xb + 1)));
    }
    __syncthreads();

    // Broadcast write: 128 channels x 64 float4 = 8192 float4 / block.
    // WRITE-THROUGH: drain to DRAM now (DRAM is idle here), so the next
    // replay's chansum doesn't eat the writeback.
    int px4  = tid & 63;
    int csub = tid >> 6;             // 0..3
    float4 v = ((const float4*)row)[px4];
    float4* o = out + ((size_t)(b * NCH + csub) * 256 + py) * 64 + px4;
#pragma unroll
    for (int i = 0; i < 32; i++) {
        __stwt(o, v);                // st.global.wt
        o += (size_t)4 * 256 * 64;   // advance 4 channels
    }
}

extern "C" void kernel_launch(void* const* d_in, const int* in_sizes, int n_in,
                              void* d_out, int out_size) {
    const float4* x = (const float4*)d_in[0];
    float4* out = (float4*)d_out;

    k_chansum<<<(NB * S_SPATIAL4 + 255) / 256, 256>>>(x);
    k_edgecast<<<NB * 256, 256>>>(out);
}

// round 8
// speedup vs baseline: 1.1900x; 1.0194x over previous
#include <cuda_runtime.h>

// Problem: x (2,128,512,512) f32.
//   edge = sum_o |conv(sum_c x, sobel_o)|  (channel-independent)
//   out  = maxpool2x2(edge) broadcast to (2,128,256,256)
//
// Single fused kernel, producer/consumer:
//   blocks 0..511   (cs): channel sum; cs block lb of batch b produces input
//                         rows {2lb, 2lb+1}; release-flag when done.
//   blocks 512..1023(ec): pooled row py of batch b: acquire-wait on cs blocks
//                         {py-1, py, py+1}, then sobel+abs+maxpool from smem
//                         and broadcast-write 128 channels (L2-store bound,
//                         overlaps the cs DRAM-read stream).
// Flags reset by a tiny kernel each launch (graph replays reuse globals).

#define S_SPATIAL   (512 * 512)
#define S_SPATIAL4  (S_SPATIAL / 4)   // 65536
#define NCH         128
#define NB          2
#define NBLK_CS     512               // 256 per batch

__device__ float g_sum[NB * S_SPATIAL];   // 2 MB scratch
__device__ int   g_flag[NBLK_CS];

__global__ void k_reset() {
    int i = blockIdx.x * blockDim.x + threadIdx.x;
    if (i < NBLK_CS) g_flag[i] = 0;
}

__device__ __forceinline__ float edge_at(const float* r0, const float* r1,
                                         const float* r2, int x0) {
    float a = r0[x0],  bb = r0[x0+1], c = r0[x0+2];
    float d = r1[x0],                  f = r1[x0+2];
    float g = r2[x0],  h = r2[x0+1],  i = r2[x0+2];
    // XLA conv = cross-correlation (no kernel flip)
    float e0 = -a + c - 2.f*d + 2.f*f - g + i;
    float e1 =  a + 2.f*bb + c - g - 2.f*h - i;
    float e2 =  2.f*a + bb + d - f - h - 2.f*i;
    float e3 = -bb - 2.f*c + d - f + 2.f*g + h;
    return fabsf(e0) + fabsf(e1) + fabsf(e2) + fabsf(e3);
}

#define SROW_W 520   // 514 used (x = -1 .. 512), padded

__global__ void __launch_bounds__(256) k_fused(const float4* __restrict__ x,
                                               float4* __restrict__ out) {
    __shared__ float srow[4][SROW_W];
    __shared__ float row[256];

    int bid = blockIdx.x;
    int tid = threadIdx.x;

    if (bid < NBLK_CS) {
        // ---------------- producer: channel sum, 2 input rows ----------------
        int idx = bid * 256 + tid;           // 0 .. 131071
        int b   = idx >> 16;
        int sp  = idx & 0xFFFF;
        const float4* p = x + (size_t)b * NCH * S_SPATIAL4 + sp;
        float4 acc = make_float4(0.f, 0.f, 0.f, 0.f);
#pragma unroll 8
        for (int c = 0; c < NCH; c++) {
            float4 v = p[(size_t)c * S_SPATIAL4];
            acc.x += v.x; acc.y += v.y; acc.z += v.z; acc.w += v.w;
        }
        ((float4*)g_sum)[idx] = acc;
        __threadfence();                     // release: g_sum visible GPU-wide
        __syncthreads();
        if (tid == 0) atomicExch(&g_flag[bid], 1);
        return;
    }

    // ---------------- consumer: edge+pool+broadcast one pooled row ----------------
    int eb = bid - NBLK_CS;
    int py = eb & 255;
    int b  = eb >> 8;

    // Acquire-wait on producer blocks (b, py-1), (b, py), (b, py+1)
    if (tid < 3) {
        int lb = py - 1 + tid;
        if (lb >= 0 && lb < 256) {
            volatile int* f = (volatile int*)&g_flag[(b << 8) | lb];
            while (*f == 0) __nanosleep(200);
        }
        __threadfence();                     // acquire
    }
    __syncthreads();

    // Stage 4 rows of g_sum via L2 (coherent), coalesced float4
    const float* s = g_sum + b * S_SPATIAL;
#pragma unroll
    for (int k = tid; k < 512; k += 256) {
        int r  = k >> 7;                     // 0..3
        int f4 = k & 127;
        int y  = 2 * py - 1 + r;
        float4 v = make_float4(0.f, 0.f, 0.f, 0.f);
        if (y >= 0 && y < 512)
            v = __ldcg((const float4*)(s + y * 512) + f4);
        float* dst = &srow[r][1 + 4 * f4];
        dst[0] = v.x; dst[1] = v.y; dst[2] = v.z; dst[3] = v.w;
    }
    if (tid < 8) {                           // halo cols x=-1, x=512 are zero
        int r = tid >> 1;
        srow[r][(tid & 1) ? 513 : 0] = 0.f;
    }
    __syncthreads();

    {
        int xb = 2 * tid;
        const float *r0 = srow[0], *r1 = srow[1], *r2 = srow[2], *r3 = srow[3];
        row[tid] = fmaxf(
            fmaxf(edge_at(r0, r1, r2, xb), edge_at(r0, r1, r2, xb + 1)),
            fmaxf(edge_at(r1, r2, r3, xb), edge_at(r1, r2, r3, xb + 1)));
    }
    __syncthreads();

    // Broadcast write: 128 channels x 64 float4 = 8192 float4 / block.
    int px4  = tid & 63;
    int csub = tid >> 6;                     // 0..3
    float4 v = ((const float4*)row)[px4];
    float4* o = out + ((size_t)(b * NCH + csub) * 256 + py) * 64 + px4;
#pragma unroll
    for (int i = 0; i < 32; i++) {
        __stcs(o, v);                        // evict-first
        o += (size_t)4 * 256 * 64;           // advance 4 channels
    }
}

extern "C" void kernel_launch(void* const* d_in, const int* in_sizes, int n_in,
                              void* d_out, int out_size) {
    const float4* x = (const float4*)d_in[0];
    float4* out = (float4*)d_out;

    k_reset<<<2, 256>>>();
    k_fused<<<NBLK_CS + NB * 256, 256>>>(x, out);
}